// round 12
// baseline (speedup 1.0000x reference)
#include <cuda_runtime.h>
#include <cuda_fp16.h>

// Problem constants (B=2, C=128, H=800, W=640, N=10000)
#define BB 2
#define CC 128
#define HH 800
#define WW 640
#define NN 10000
#define HW (HH * WW)      // 512000
#define TPX 64            // pixels per transpose tile

// Scratch: NHWC fp16 hi/lo split of the image.
//  g_h = fp16(x)            -> value path (36 taps)
//  g_l = fp16(x - fp16(x))  -> center/delta path reconstructs x ~ 2^-22 rel
__device__ __half g_h[(size_t)BB * HW * CC];   // 262 MB
__device__ __half g_l[(size_t)BB * HW * CC];   // 262 MB

__device__ __forceinline__ float clampf(float v, float lo, float hi) {
    return fminf(fmaxf(v, lo), hi);
}

// ---------------------------------------------------------------------------
// k_half: transpose (B,C,H,W) fp32 -> (B,H,W,C) fp16 hi + fp16 lo.
// grid = (HW/64, C/32, B), block = 256. At its byte floor (~5.6 TB/s).
// ---------------------------------------------------------------------------
__global__ void __launch_bounds__(256) k_half(const float* __restrict__ img)
{
    __shared__ float tile[32][TPX + 1];            // [c_local][px]
    const int b   = blockIdx.z;
    const int c0  = blockIdx.y * 32;
    const int hw0 = blockIdx.x * TPX;
    const int tid = threadIdx.x;

    // staging: 32 rows x 64 px, warp = 32 contiguous px of one c row
    const float* __restrict__ src = img + ((size_t)b * CC + c0) * HW + hw0;
    #pragma unroll
    for (int it = 0; it < 8; it++) {
        const int i  = it * 256 + tid;
        const int px = i & 63;
        const int c  = i >> 6;
        tile[c][px] = __ldcs(src + (size_t)c * HW + px);
    }
    __syncthreads();

    // dump: thread = (px, channel octet). 8 scalar LDS (conflict-free),
    // packed f32->f16 hi + exact residual -> f16 lo, one uint4 store per plane.
    const int px = tid >> 2;        // 0..63
    const int q  = tid & 3;         // octet 0..3 -> channels 8q..8q+7
    float v[8];
    #pragma unroll
    for (int j = 0; j < 8; j++) v[j] = tile[8 * q + j][px];

    uint4 uh, ul;
    unsigned int* ph = reinterpret_cast<unsigned int*>(&uh);
    unsigned int* pl = reinterpret_cast<unsigned int*>(&ul);
    #pragma unroll
    for (int j = 0; j < 4; j++) {
        const float2 f = make_float2(v[2 * j], v[2 * j + 1]);
        const __half2 h2 = __float22half2_rn(f);
        const float2 fb = __half22float2(h2);
        const float2 r = make_float2(f.x - fb.x, f.y - fb.y);   // exact
        const __half2 l2 = __float22half2_rn(r);
        ph[j] = *reinterpret_cast<const unsigned int*>(&h2);
        pl[j] = *reinterpret_cast<const unsigned int*>(&l2);
    }
    const size_t off = (size_t)(b * HW + hw0 + px) * CC + c0 + 8 * q;
    *reinterpret_cast<uint4*>(g_h + off) = uh;
    *reinterpret_cast<uint4*>(g_l + off) = ul;
}

// ---------------------------------------------------------------------------
// k_sample: one block per point (128 threads).
//  A) center sample: warp = tap, lane = 4 ch, LDG.64 hi + LDG.64 lo;
//     hi values kept in registers and reused as phase D location 0.
//  B) 18-dot: 8 lanes/output, float4 loads, shfl reduce
//  C) 8 learnt locations -> tap offsets + weights
//  D) 8 neighbor taps per warp: ALL loads front-batched into registers
//     (MLP=8, ~2KB in flight per warp) before any conversion/FMA.
// ---------------------------------------------------------------------------
__global__ void __launch_bounds__(128) k_sample(
    const float* __restrict__ verts,
    const float* __restrict__ cw,
    const float* __restrict__ cb,
    float* __restrict__ out)
{
    const int p = blockIdx.x;            // 0 .. B*N-1
    const int b = p / NN;
    const int tid = threadIdx.x;
    const int lane = tid & 31, grp = tid >> 5;

    __shared__ float redA[4][CC];
    __shared__ float sf[CC];
    __shared__ float sd[16];
    __shared__ int   soff[9][4];
    __shared__ float swt[9][4];

    const float vx = verts[p * 2 + 0];
    const float vy = verts[p * 2 + 1];

    const float gx = clampf((vx + 1.0f) * 0.5f * (WW - 1), 0.0f, (float)(WW - 1));
    const float gy = clampf((vy + 1.0f) * 0.5f * (HH - 1), 0.0f, (float)(HH - 1));
    const int x0 = (int)floorf(gx), y0 = (int)floorf(gy);
    const int x1 = min(x0 + 1, WW - 1), y1 = min(y0 + 1, HH - 1);
    const float wx1 = gx - (float)x0, wy1 = gy - (float)y0;
    const float wx0 = 1.0f - wx1, wy0 = 1.0f - wy1;

    const size_t base = (size_t)b * HW * CC;

    // ---- A: center feature, warp = tap, lane = 4 channels.
    //      hi values (h0,h1) stay live: they are phase D's location 0.
    float2 h0, h1;
    float wA;
    {
        const int cx = (grp & 1) ? x1 : x0;
        const int cy = (grp & 2) ? y1 : y0;
        wA = ((grp & 1) ? wx1 : wx0) * ((grp & 2) ? wy1 : wy0);
        const size_t o = base + (size_t)(cy * WW + cx) * CC + lane * 4;
        const uint2 uh = *reinterpret_cast<const uint2*>(g_h + o);
        const uint2 ul = *reinterpret_cast<const uint2*>(g_l + o);
        h0 = __half22float2(*reinterpret_cast<const __half2*>(&uh.x));
        h1 = __half22float2(*reinterpret_cast<const __half2*>(&uh.y));
        const float2 l0 = __half22float2(*reinterpret_cast<const __half2*>(&ul.x));
        const float2 l1 = __half22float2(*reinterpret_cast<const __half2*>(&ul.y));
        float4 f;
        f.x = (h0.x + l0.x) * wA;
        f.y = (h0.y + l0.y) * wA;
        f.z = (h1.x + l1.x) * wA;
        f.w = (h1.y + l1.y) * wA;
        *reinterpret_cast<float4*>(&redA[grp][lane * 4]) = f;
    }
    __syncthreads();
    sf[tid] = redA[0][tid] + redA[1][tid] + redA[2][tid] + redA[3][tid];
    __syncthreads();

    // ---- B: deltas = conv rows 2..17 dot center feature (float4 loads) ----
    {
        const int o = tid >> 3;          // 0..15
        const int g = tid & 7;           // 8 lanes per output
        const float4* __restrict__ wv =
            reinterpret_cast<const float4*>(cw + (o + 2) * CC + g * 16);
        const float4* __restrict__ fv = reinterpret_cast<const float4*>(sf + g * 16);
        float acc = 0.0f;
        #pragma unroll
        for (int i = 0; i < 4; i++) {
            const float4 w4 = wv[i];
            const float4 f4 = fv[i];
            acc = fmaf(f4.x, w4.x, acc);
            acc = fmaf(f4.y, w4.y, acc);
            acc = fmaf(f4.z, w4.z, acc);
            acc = fmaf(f4.w, w4.w, acc);
        }
        acc += __shfl_down_sync(0xffffffffu, acc, 4);
        acc += __shfl_down_sync(0xffffffffu, acc, 2);
        acc += __shfl_down_sync(0xffffffffu, acc, 1);
        if (g == 0) sd[o] = acc + cb[o + 2];
    }
    __syncthreads();

    // ---- C: 8 learnt neighbor locations -> tap offsets + weights ----
    if (tid >= 1 && tid < 9) {
        const float nx = vx + sd[2 * tid - 2];
        const float ny = vy + sd[2 * tid - 1];
        const float ggx = clampf((nx + 1.0f) * 0.5f * (WW - 1), 0.0f, (float)(WW - 1));
        const float ggy = clampf((ny + 1.0f) * 0.5f * (HH - 1), 0.0f, (float)(HH - 1));
        const int nx0 = (int)floorf(ggx), ny0 = (int)floorf(ggy);
        const int nx1 = min(nx0 + 1, WW - 1), ny1 = min(ny0 + 1, HH - 1);
        const float nwx1 = ggx - (float)nx0, nwy1 = ggy - (float)ny0;
        const float nwx0 = 1.0f - nwx1, nwy0 = 1.0f - nwy1;
        soff[tid][0] = (ny0 * WW + nx0) * CC;
        soff[tid][1] = (ny0 * WW + nx1) * CC;
        soff[tid][2] = (ny1 * WW + nx0) * CC;
        soff[tid][3] = (ny1 * WW + nx1) * CC;
        const float s = 1.0f / 9.0f;
        swt[tid][0] = nwy0 * nwx0 * s;
        swt[tid][1] = nwy0 * nwx1 * s;
        swt[tid][2] = nwy1 * nwx0 * s;
        swt[tid][3] = nwy1 * nwx1 * s;
    }
    __syncthreads();

    // ---- D: locations 1..8 — LOADS FIRST (MLP=8), then accumulate ----
    const __half* hb = g_h + base + lane * 4;

    uint2 u[8];
    #pragma unroll
    for (int i = 0; i < 8; i++)
        u[i] = *reinterpret_cast<const uint2*>(hb + soff[i + 1][grp]);

    const float w0 = wA * (1.0f / 9.0f);
    float ax = h0.x * w0, ay = h0.y * w0;
    float az = h1.x * w0, aw = h1.y * w0;

    #pragma unroll
    for (int i = 0; i < 8; i++) {
        const float w = swt[i + 1][grp];
        const float2 f0 = __half22float2(*reinterpret_cast<const __half2*>(&u[i].x));
        const float2 f1 = __half22float2(*reinterpret_cast<const __half2*>(&u[i].y));
        ax = fmaf(w, f0.x, ax); ay = fmaf(w, f0.y, ay);
        az = fmaf(w, f1.x, az); aw = fmaf(w, f1.y, aw);
    }

    __shared__ float4 red[4][32];
    red[grp][lane] = make_float4(ax, ay, az, aw);
    __syncthreads();

    if (tid < 32) {
        const float4 r0 = red[0][tid], r1 = red[1][tid];
        const float4 r2 = red[2][tid], r3 = red[3][tid];
        float4 o4;
        o4.x = r0.x + r1.x + r2.x + r3.x;
        o4.y = r0.y + r1.y + r2.y + r3.y;
        o4.z = r0.z + r1.z + r2.z + r3.z;
        o4.w = r0.w + r1.w + r2.w + r3.w;
        reinterpret_cast<float4*>(out)[(size_t)p * 32 + tid] = o4;
    }
}

extern "C" void kernel_launch(void* const* d_in, const int* in_sizes, int n_in,
                              void* d_out, int out_size)
{
    const float* img   = (const float*)d_in[0];   // (B, C, H, W)
    const float* verts = (const float*)d_in[1];   // (B, N, 2)
    const float* cw    = (const float*)d_in[2];   // (18, C)
    const float* cb    = (const float*)d_in[3];   // (18,)
    float* out = (float*)d_out;                   // (B, N, C)

    dim3 tgrid(HW / TPX, CC / 32, BB);
    k_half<<<tgrid, 256>>>(img);

    k_sample<<<BB * NN, 128>>>(verts, cw, cb, out);
}

// round 14
// speedup vs baseline: 1.0757x; 1.0757x over previous
#include <cuda_runtime.h>
#include <cuda_fp16.h>

// Problem constants (B=2, C=128, H=800, W=640, N=10000)
#define BB 2
#define CC 128
#define HH 800
#define WW 640
#define NN 10000
#define HW (HH * WW)      // 512000
#define TPX 64            // pixels per transpose tile

// Scratch: NHWC fp16 hi plane (full) + lo plane (only at center-tap pixels).
//  g_h = fp16(x)            -> value path (36 taps)
//  g_l = fp16(x - fp16(x))  -> center/delta path; written only where needed
__device__ __half g_h[(size_t)BB * HW * CC];       // 262 MB
__device__ __half g_l[(size_t)BB * HW * CC];       // 262 MB (sparsely written)
__device__ unsigned char g_mark[(size_t)BB * HW];  // 1 MB: pixel needs lo plane

__device__ __forceinline__ float clampf(float v, float lo, float hi) {
    return fminf(fmaxf(v, lo), hi);
}

// ---------------------------------------------------------------------------
// k_mark: thread = point; mark the 4 center-tap pixels. Idempotent stores.
// ---------------------------------------------------------------------------
__global__ void __launch_bounds__(256) k_mark(const float* __restrict__ verts)
{
    const int p = blockIdx.x * 256 + threadIdx.x;
    if (p >= BB * NN) return;
    const int b = p / NN;

    const float vx = verts[p * 2 + 0];
    const float vy = verts[p * 2 + 1];
    const float gx = clampf((vx + 1.0f) * 0.5f * (WW - 1), 0.0f, (float)(WW - 1));
    const float gy = clampf((vy + 1.0f) * 0.5f * (HH - 1), 0.0f, (float)(HH - 1));
    const int x0 = (int)floorf(gx), y0 = (int)floorf(gy);
    const int x1 = min(x0 + 1, WW - 1), y1 = min(y0 + 1, HH - 1);

    unsigned char* m = g_mark + (size_t)b * HW;
    m[y0 * WW + x0] = 1;
    m[y0 * WW + x1] = 1;
    m[y1 * WW + x0] = 1;
    m[y1 * WW + x1] = 1;
}

// ---------------------------------------------------------------------------
// k_half: transpose (B,C,H,W) fp32 -> (B,H,W,C) fp16 hi (always) + lo (only
// at marked pixels). grid = (HW/64, C/32, B), block = 256.
// ---------------------------------------------------------------------------
__global__ void __launch_bounds__(256) k_half(const float* __restrict__ img)
{
    __shared__ float tile[32][TPX + 1];            // [c_local][px]
    const int b   = blockIdx.z;
    const int c0  = blockIdx.y * 32;
    const int hw0 = blockIdx.x * TPX;
    const int tid = threadIdx.x;

    // staging: 32 rows x 64 px, warp = 32 contiguous px of one c row
    const float* __restrict__ src = img + ((size_t)b * CC + c0) * HW + hw0;
    #pragma unroll
    for (int it = 0; it < 8; it++) {
        const int i  = it * 256 + tid;
        const int px = i & 63;
        const int c  = i >> 6;
        tile[c][px] = __ldcs(src + (size_t)c * HW + px);
    }
    __syncthreads();

    // dump: thread = (px, channel octet). hi always; lo only if pixel marked.
    const int px = tid >> 2;        // 0..63
    const int q  = tid & 3;         // octet 0..3 -> channels 8q..8q+7
    const bool need_lo = g_mark[(size_t)b * HW + hw0 + px] != 0;

    float v[8];
    #pragma unroll
    for (int j = 0; j < 8; j++) v[j] = tile[8 * q + j][px];

    uint4 uh, ul;
    unsigned int* ph = reinterpret_cast<unsigned int*>(&uh);
    unsigned int* pl = reinterpret_cast<unsigned int*>(&ul);
    #pragma unroll
    for (int j = 0; j < 4; j++) {
        const float2 f = make_float2(v[2 * j], v[2 * j + 1]);
        const __half2 h2 = __float22half2_rn(f);
        const float2 fb = __half22float2(h2);
        const float2 r = make_float2(f.x - fb.x, f.y - fb.y);   // exact
        const __half2 l2 = __float22half2_rn(r);
        ph[j] = *reinterpret_cast<const unsigned int*>(&h2);
        pl[j] = *reinterpret_cast<const unsigned int*>(&l2);
    }
    const size_t off = (size_t)(b * HW + hw0 + px) * CC + c0 + 8 * q;
    *reinterpret_cast<uint4*>(g_h + off) = uh;
    if (need_lo)
        *reinterpret_cast<uint4*>(g_l + off) = ul;
}

// ---------------------------------------------------------------------------
// k_sample: one block per point (128 threads). Unchanged from R12.
// ---------------------------------------------------------------------------
__global__ void __launch_bounds__(128) k_sample(
    const float* __restrict__ verts,
    const float* __restrict__ cw,
    const float* __restrict__ cb,
    float* __restrict__ out)
{
    const int p = blockIdx.x;            // 0 .. B*N-1
    const int b = p / NN;
    const int tid = threadIdx.x;
    const int lane = tid & 31, grp = tid >> 5;

    __shared__ float redA[4][CC];
    __shared__ float sf[CC];
    __shared__ float sd[16];
    __shared__ int   soff[9][4];
    __shared__ float swt[9][4];

    const float vx = verts[p * 2 + 0];
    const float vy = verts[p * 2 + 1];

    const float gx = clampf((vx + 1.0f) * 0.5f * (WW - 1), 0.0f, (float)(WW - 1));
    const float gy = clampf((vy + 1.0f) * 0.5f * (HH - 1), 0.0f, (float)(HH - 1));
    const int x0 = (int)floorf(gx), y0 = (int)floorf(gy);
    const int x1 = min(x0 + 1, WW - 1), y1 = min(y0 + 1, HH - 1);
    const float wx1 = gx - (float)x0, wy1 = gy - (float)y0;
    const float wx0 = 1.0f - wx1, wy0 = 1.0f - wy1;

    const size_t base = (size_t)b * HW * CC;

    // ---- A: center feature, warp = tap, lane = 4 channels ----
    float2 h0, h1;
    float wA;
    {
        const int cx = (grp & 1) ? x1 : x0;
        const int cy = (grp & 2) ? y1 : y0;
        wA = ((grp & 1) ? wx1 : wx0) * ((grp & 2) ? wy1 : wy0);
        const size_t o = base + (size_t)(cy * WW + cx) * CC + lane * 4;
        const uint2 uh = *reinterpret_cast<const uint2*>(g_h + o);
        const uint2 ul = *reinterpret_cast<const uint2*>(g_l + o);
        h0 = __half22float2(*reinterpret_cast<const __half2*>(&uh.x));
        h1 = __half22float2(*reinterpret_cast<const __half2*>(&uh.y));
        const float2 l0 = __half22float2(*reinterpret_cast<const __half2*>(&ul.x));
        const float2 l1 = __half22float2(*reinterpret_cast<const __half2*>(&ul.y));
        float4 f;
        f.x = (h0.x + l0.x) * wA;
        f.y = (h0.y + l0.y) * wA;
        f.z = (h1.x + l1.x) * wA;
        f.w = (h1.y + l1.y) * wA;
        *reinterpret_cast<float4*>(&redA[grp][lane * 4]) = f;
    }
    __syncthreads();
    sf[tid] = redA[0][tid] + redA[1][tid] + redA[2][tid] + redA[3][tid];
    __syncthreads();

    // ---- B: deltas = conv rows 2..17 dot center feature (float4 loads) ----
    {
        const int o = tid >> 3;          // 0..15
        const int g = tid & 7;           // 8 lanes per output
        const float4* __restrict__ wv =
            reinterpret_cast<const float4*>(cw + (o + 2) * CC + g * 16);
        const float4* __restrict__ fv = reinterpret_cast<const float4*>(sf + g * 16);
        float acc = 0.0f;
        #pragma unroll
        for (int i = 0; i < 4; i++) {
            const float4 w4 = wv[i];
            const float4 f4 = fv[i];
            acc = fmaf(f4.x, w4.x, acc);
            acc = fmaf(f4.y, w4.y, acc);
            acc = fmaf(f4.z, w4.z, acc);
            acc = fmaf(f4.w, w4.w, acc);
        }
        acc += __shfl_down_sync(0xffffffffu, acc, 4);
        acc += __shfl_down_sync(0xffffffffu, acc, 2);
        acc += __shfl_down_sync(0xffffffffu, acc, 1);
        if (g == 0) sd[o] = acc + cb[o + 2];
    }
    __syncthreads();

    // ---- C: 8 learnt neighbor locations -> tap offsets + weights ----
    if (tid >= 1 && tid < 9) {
        const float nx = vx + sd[2 * tid - 2];
        const float ny = vy + sd[2 * tid - 1];
        const float ggx = clampf((nx + 1.0f) * 0.5f * (WW - 1), 0.0f, (float)(WW - 1));
        const float ggy = clampf((ny + 1.0f) * 0.5f * (HH - 1), 0.0f, (float)(HH - 1));
        const int nx0 = (int)floorf(ggx), ny0 = (int)floorf(ggy);
        const int nx1 = min(nx0 + 1, WW - 1), ny1 = min(ny0 + 1, HH - 1);
        const float nwx1 = ggx - (float)nx0, nwy1 = ggy - (float)ny0;
        const float nwx0 = 1.0f - nwx1, nwy0 = 1.0f - nwy1;
        soff[tid][0] = (ny0 * WW + nx0) * CC;
        soff[tid][1] = (ny0 * WW + nx1) * CC;
        soff[tid][2] = (ny1 * WW + nx0) * CC;
        soff[tid][3] = (ny1 * WW + nx1) * CC;
        const float s = 1.0f / 9.0f;
        swt[tid][0] = nwy0 * nwx0 * s;
        swt[tid][1] = nwy0 * nwx1 * s;
        swt[tid][2] = nwy1 * nwx0 * s;
        swt[tid][3] = nwy1 * nwx1 * s;
    }
    __syncthreads();

    // ---- D: locations 1..8 (center contribution seeded from phase A regs) ----
    const __half* hb = g_h + base + lane * 4;

    uint2 u[8];
    #pragma unroll
    for (int i = 0; i < 8; i++)
        u[i] = *reinterpret_cast<const uint2*>(hb + soff[i + 1][grp]);

    const float w0 = wA * (1.0f / 9.0f);
    float ax = h0.x * w0, ay = h0.y * w0;
    float az = h1.x * w0, aw = h1.y * w0;

    #pragma unroll
    for (int i = 0; i < 8; i++) {
        const float w = swt[i + 1][grp];
        const float2 f0 = __half22float2(*reinterpret_cast<const __half2*>(&u[i].x));
        const float2 f1 = __half22float2(*reinterpret_cast<const __half2*>(&u[i].y));
        ax = fmaf(w, f0.x, ax); ay = fmaf(w, f0.y, ay);
        az = fmaf(w, f1.x, az); aw = fmaf(w, f1.y, aw);
    }

    __shared__ float4 red[4][32];
    red[grp][lane] = make_float4(ax, ay, az, aw);
    __syncthreads();

    if (tid < 32) {
        const float4 r0 = red[0][tid], r1 = red[1][tid];
        const float4 r2 = red[2][tid], r3 = red[3][tid];
        float4 o4;
        o4.x = r0.x + r1.x + r2.x + r3.x;
        o4.y = r0.y + r1.y + r2.y + r3.y;
        o4.z = r0.z + r1.z + r2.z + r3.z;
        o4.w = r0.w + r1.w + r2.w + r3.w;
        reinterpret_cast<float4*>(out)[(size_t)p * 32 + tid] = o4;
    }
}

extern "C" void kernel_launch(void* const* d_in, const int* in_sizes, int n_in,
                              void* d_out, int out_size)
{
    const float* img   = (const float*)d_in[0];   // (B, C, H, W)
    const float* verts = (const float*)d_in[1];   // (B, N, 2)
    const float* cw    = (const float*)d_in[2];   // (18, C)
    const float* cb    = (const float*)d_in[3];   // (18,)
    float* out = (float*)d_out;                   // (B, N, C)

    // clear mark map (capturable memset node; no allocation)
    void* mark_ptr = nullptr;
    cudaGetSymbolAddress(&mark_ptr, g_mark);
    cudaMemsetAsync(mark_ptr, 0, (size_t)BB * HW);

    k_mark<<<(BB * NN + 255) / 256, 256>>>(verts);

    dim3 tgrid(HW / TPX, CC / 32, BB);
    k_half<<<tgrid, 256>>>(img);

    k_sample<<<BB * NN, 128>>>(verts, cw, cb, out);
}

// round 15
// speedup vs baseline: 1.0878x; 1.0113x over previous
#include <cuda_runtime.h>
#include <cuda_fp16.h>

// Problem constants (B=2, C=128, H=800, W=640, N=10000)
#define BB 2
#define CC 128
#define HH 800
#define WW 640
#define NN 10000
#define HW (HH * WW)      // 512000
#define TPX 64            // pixels per transpose tile

// Scratch: NHWC fp16 hi plane (full) + lo plane (only at center-tap pixels).
//  g_h = fp16(x)            -> value path (36 taps)
//  g_l = fp16(x - fp16(x))  -> center/delta path; written only where needed
__device__ __half g_h[(size_t)BB * HW * CC];       // 262 MB
__device__ __half g_l[(size_t)BB * HW * CC];       // 262 MB (sparsely written)
__device__ unsigned char g_mark[(size_t)BB * HW];  // 1 MB: pixel needs lo plane

__device__ __forceinline__ float clampf(float v, float lo, float hi) {
    return fminf(fmaxf(v, lo), hi);
}

// ---------------------------------------------------------------------------
// k_mark: thread = point; mark the 4 center-tap pixels. Idempotent stores.
// ---------------------------------------------------------------------------
__global__ void __launch_bounds__(256) k_mark(const float* __restrict__ verts)
{
    const int p = blockIdx.x * 256 + threadIdx.x;
    if (p >= BB * NN) return;
    const int b = p / NN;

    const float vx = verts[p * 2 + 0];
    const float vy = verts[p * 2 + 1];
    const float gx = clampf((vx + 1.0f) * 0.5f * (WW - 1), 0.0f, (float)(WW - 1));
    const float gy = clampf((vy + 1.0f) * 0.5f * (HH - 1), 0.0f, (float)(HH - 1));
    const int x0 = (int)floorf(gx), y0 = (int)floorf(gy);
    const int x1 = min(x0 + 1, WW - 1), y1 = min(y0 + 1, HH - 1);

    unsigned char* m = g_mark + (size_t)b * HW;
    m[y0 * WW + x0] = 1;
    m[y0 * WW + x1] = 1;
    m[y1 * WW + x0] = 1;
    m[y1 * WW + x1] = 1;
}

// ---------------------------------------------------------------------------
// k_half: transpose (B,C,H,W) fp32 -> (B,H,W,C) fp16 hi (always) + lo (only
// at marked pixels). grid = (HW/64, C/32, B), block = 256.
// ---------------------------------------------------------------------------
__global__ void __launch_bounds__(256) k_half(const float* __restrict__ img)
{
    __shared__ float tile[32][TPX + 1];            // [c_local][px]
    const int b   = blockIdx.z;
    const int c0  = blockIdx.y * 32;
    const int hw0 = blockIdx.x * TPX;
    const int tid = threadIdx.x;

    // staging: 32 rows x 64 px, warp = 32 contiguous px of one c row
    const float* __restrict__ src = img + ((size_t)b * CC + c0) * HW + hw0;
    #pragma unroll
    for (int it = 0; it < 8; it++) {
        const int i  = it * 256 + tid;
        const int px = i & 63;
        const int c  = i >> 6;
        tile[c][px] = __ldcs(src + (size_t)c * HW + px);
    }
    __syncthreads();

    // dump: thread = (px, channel octet). hi always; lo only if pixel marked.
    const int px = tid >> 2;        // 0..63
    const int q  = tid & 3;         // octet 0..3 -> channels 8q..8q+7
    const bool need_lo = g_mark[(size_t)b * HW + hw0 + px] != 0;

    float v[8];
    #pragma unroll
    for (int j = 0; j < 8; j++) v[j] = tile[8 * q + j][px];

    uint4 uh, ul;
    unsigned int* ph = reinterpret_cast<unsigned int*>(&uh);
    unsigned int* pl = reinterpret_cast<unsigned int*>(&ul);
    #pragma unroll
    for (int j = 0; j < 4; j++) {
        const float2 f = make_float2(v[2 * j], v[2 * j + 1]);
        const __half2 h2 = __float22half2_rn(f);
        const float2 fb = __half22float2(h2);
        const float2 r = make_float2(f.x - fb.x, f.y - fb.y);   // exact
        const __half2 l2 = __float22half2_rn(r);
        ph[j] = *reinterpret_cast<const unsigned int*>(&h2);
        pl[j] = *reinterpret_cast<const unsigned int*>(&l2);
    }
    const size_t off = (size_t)(b * HW + hw0 + px) * CC + c0 + 8 * q;
    *reinterpret_cast<uint4*>(g_h + off) = uh;
    if (need_lo)
        *reinterpret_cast<uint4*>(g_l + off) = ul;
}

// ---------------------------------------------------------------------------
// k_sample: one block per point (128 threads), forced 16 blocks/SM (32 regs)
// so the latency-bound gather gets ~2x more misses in flight.
// ---------------------------------------------------------------------------
__global__ void __launch_bounds__(128, 16) k_sample(
    const float* __restrict__ verts,
    const float* __restrict__ cw,
    const float* __restrict__ cb,
    float* __restrict__ out)
{
    const int p = blockIdx.x;            // 0 .. B*N-1
    const int b = p / NN;
    const int tid = threadIdx.x;
    const int lane = tid & 31, grp = tid >> 5;

    __shared__ float redA[4][CC];
    __shared__ float sf[CC];
    __shared__ float sd[16];
    __shared__ int   soff[9][4];
    __shared__ float swt[9][4];

    const float vx = verts[p * 2 + 0];
    const float vy = verts[p * 2 + 1];

    const float gx = clampf((vx + 1.0f) * 0.5f * (WW - 1), 0.0f, (float)(WW - 1));
    const float gy = clampf((vy + 1.0f) * 0.5f * (HH - 1), 0.0f, (float)(HH - 1));
    const int x0 = (int)floorf(gx), y0 = (int)floorf(gy);
    const int x1 = min(x0 + 1, WW - 1), y1 = min(y0 + 1, HH - 1);
    const float wx1 = gx - (float)x0, wy1 = gy - (float)y0;
    const float wx0 = 1.0f - wx1, wy0 = 1.0f - wy1;

    const size_t base = (size_t)b * HW * CC;

    // ---- A: center feature, warp = tap, lane = 4 channels.
    //      hi values (h0,h1) stay live: they are phase D's location 0.
    float2 h0, h1;
    float wA;
    {
        const int cx = (grp & 1) ? x1 : x0;
        const int cy = (grp & 2) ? y1 : y0;
        wA = ((grp & 1) ? wx1 : wx0) * ((grp & 2) ? wy1 : wy0);
        const size_t o = base + (size_t)(cy * WW + cx) * CC + lane * 4;
        const uint2 uh = *reinterpret_cast<const uint2*>(g_h + o);
        const uint2 ul = *reinterpret_cast<const uint2*>(g_l + o);
        h0 = __half22float2(*reinterpret_cast<const __half2*>(&uh.x));
        h1 = __half22float2(*reinterpret_cast<const __half2*>(&uh.y));
        const float2 l0 = __half22float2(*reinterpret_cast<const __half2*>(&ul.x));
        const float2 l1 = __half22float2(*reinterpret_cast<const __half2*>(&ul.y));
        float4 f;
        f.x = (h0.x + l0.x) * wA;
        f.y = (h0.y + l0.y) * wA;
        f.z = (h1.x + l1.x) * wA;
        f.w = (h1.y + l1.y) * wA;
        *reinterpret_cast<float4*>(&redA[grp][lane * 4]) = f;
    }
    __syncthreads();
    sf[tid] = redA[0][tid] + redA[1][tid] + redA[2][tid] + redA[3][tid];
    __syncthreads();

    // ---- B: deltas = conv rows 2..17 dot center feature (float4 loads) ----
    {
        const int o = tid >> 3;          // 0..15
        const int g = tid & 7;           // 8 lanes per output
        const float4* __restrict__ wv =
            reinterpret_cast<const float4*>(cw + (o + 2) * CC + g * 16);
        const float4* __restrict__ fv = reinterpret_cast<const float4*>(sf + g * 16);
        float acc = 0.0f;
        #pragma unroll
        for (int i = 0; i < 4; i++) {
            const float4 w4 = wv[i];
            const float4 f4 = fv[i];
            acc = fmaf(f4.x, w4.x, acc);
            acc = fmaf(f4.y, w4.y, acc);
            acc = fmaf(f4.z, w4.z, acc);
            acc = fmaf(f4.w, w4.w, acc);
        }
        acc += __shfl_down_sync(0xffffffffu, acc, 4);
        acc += __shfl_down_sync(0xffffffffu, acc, 2);
        acc += __shfl_down_sync(0xffffffffu, acc, 1);
        if (g == 0) sd[o] = acc + cb[o + 2];
    }
    __syncthreads();

    // ---- C: 8 learnt neighbor locations -> tap offsets + weights ----
    if (tid >= 1 && tid < 9) {
        const float nx = vx + sd[2 * tid - 2];
        const float ny = vy + sd[2 * tid - 1];
        const float ggx = clampf((nx + 1.0f) * 0.5f * (WW - 1), 0.0f, (float)(WW - 1));
        const float ggy = clampf((ny + 1.0f) * 0.5f * (HH - 1), 0.0f, (float)(HH - 1));
        const int nx0 = (int)floorf(ggx), ny0 = (int)floorf(ggy);
        const int nx1 = min(nx0 + 1, WW - 1), ny1 = min(ny0 + 1, HH - 1);
        const float nwx1 = ggx - (float)nx0, nwy1 = ggy - (float)ny0;
        const float nwx0 = 1.0f - nwx1, nwy0 = 1.0f - nwy1;
        soff[tid][0] = (ny0 * WW + nx0) * CC;
        soff[tid][1] = (ny0 * WW + nx1) * CC;
        soff[tid][2] = (ny1 * WW + nx0) * CC;
        soff[tid][3] = (ny1 * WW + nx1) * CC;
        const float s = 1.0f / 9.0f;
        swt[tid][0] = nwy0 * nwx0 * s;
        swt[tid][1] = nwy0 * nwx1 * s;
        swt[tid][2] = nwy1 * nwx0 * s;
        swt[tid][3] = nwy1 * nwx1 * s;
    }
    __syncthreads();

    // ---- D: locations 1..8 (center contribution seeded from phase A regs) ----
    const __half* hb = g_h + base + lane * 4;
    const float w0 = wA * (1.0f / 9.0f);
    float ax = h0.x * w0, ay = h0.y * w0;
    float az = h1.x * w0, aw = h1.y * w0;

    #pragma unroll
    for (int i = 1; i < 9; i++) {
        const int off = soff[i][grp];
        const float w = swt[i][grp];
        const uint2 u = *reinterpret_cast<const uint2*>(hb + off);
        const float2 f0 = __half22float2(*reinterpret_cast<const __half2*>(&u.x));
        const float2 f1 = __half22float2(*reinterpret_cast<const __half2*>(&u.y));
        ax = fmaf(w, f0.x, ax); ay = fmaf(w, f0.y, ay);
        az = fmaf(w, f1.x, az); aw = fmaf(w, f1.y, aw);
    }

    __shared__ float4 red[4][32];
    red[grp][lane] = make_float4(ax, ay, az, aw);
    __syncthreads();

    if (tid < 32) {
        const float4 r0 = red[0][tid], r1 = red[1][tid];
        const float4 r2 = red[2][tid], r3 = red[3][tid];
        float4 o4;
        o4.x = r0.x + r1.x + r2.x + r3.x;
        o4.y = r0.y + r1.y + r2.y + r3.y;
        o4.z = r0.z + r1.z + r2.z + r3.z;
        o4.w = r0.w + r1.w + r2.w + r3.w;
        reinterpret_cast<float4*>(out)[(size_t)p * 32 + tid] = o4;
    }
}

extern "C" void kernel_launch(void* const* d_in, const int* in_sizes, int n_in,
                              void* d_out, int out_size)
{
    const float* img   = (const float*)d_in[0];   // (B, C, H, W)
    const float* verts = (const float*)d_in[1];   // (B, N, 2)
    const float* cw    = (const float*)d_in[2];   // (18, C)
    const float* cb    = (const float*)d_in[3];   // (18,)
    float* out = (float*)d_out;                   // (B, N, C)

    // clear mark map (capturable memset node; no allocation)
    void* mark_ptr = nullptr;
    cudaGetSymbolAddress(&mark_ptr, g_mark);
    cudaMemsetAsync(mark_ptr, 0, (size_t)BB * HW);

    k_mark<<<(BB * NN + 255) / 256, 256>>>(verts);

    dim3 tgrid(HW / TPX, CC / 32, BB);
    k_half<<<tgrid, 256>>>(img);

    k_sample<<<BB * NN, 128>>>(verts, cw, cb, out);
}

// round 16
// speedup vs baseline: 1.1446x; 1.0522x over previous
#include <cuda_runtime.h>
#include <cuda_fp16.h>

// Problem constants (B=2, C=128, H=800, W=640, N=10000)
#define BB 2
#define CC 128
#define HH 800
#define WW 640
#define NN 10000
#define HW (HH * WW)      // 512000
#define TPX 64            // pixels per transpose tile

// Scratch
__device__ __half g_h[(size_t)BB * HW * CC];       // 262 MB  fp16 hi plane (full)
__device__ __half g_l[(size_t)BB * HW * CC];       // 262 MB  fp16 lo plane (sparse)
__device__ unsigned char g_mark[(size_t)BB * HW];  // 1 MB    pixel needs lo plane
__device__ int4   g_soff[(size_t)BB * NN * 9];     // 2.9 MB  tap offsets per location
__device__ float4 g_swt [(size_t)BB * NN * 9];     // 2.9 MB  tap weights  per location

__device__ __forceinline__ float clampf(float v, float lo, float hi) {
    return fminf(fmaxf(v, lo), hi);
}

// ---------------------------------------------------------------------------
// k_mark: thread = point; mark the 4 center-tap pixels. Idempotent stores.
// ---------------------------------------------------------------------------
__global__ void __launch_bounds__(256) k_mark(const float* __restrict__ verts)
{
    const int p = blockIdx.x * 256 + threadIdx.x;
    if (p >= BB * NN) return;
    const int b = p / NN;

    const float vx = verts[p * 2 + 0];
    const float vy = verts[p * 2 + 1];
    const float gx = clampf((vx + 1.0f) * 0.5f * (WW - 1), 0.0f, (float)(WW - 1));
    const float gy = clampf((vy + 1.0f) * 0.5f * (HH - 1), 0.0f, (float)(HH - 1));
    const int x0 = (int)floorf(gx), y0 = (int)floorf(gy);
    const int x1 = min(x0 + 1, WW - 1), y1 = min(y0 + 1, HH - 1);

    unsigned char* m = g_mark + (size_t)b * HW;
    m[y0 * WW + x0] = 1;
    m[y0 * WW + x1] = 1;
    m[y1 * WW + x0] = 1;
    m[y1 * WW + x1] = 1;
}

// ---------------------------------------------------------------------------
// k_half: transpose (B,C,H,W) fp32 -> (B,H,W,C) fp16 hi (always) + lo (only
// at marked pixels). grid = (HW/64, C/32, B), block = 256.
// ---------------------------------------------------------------------------
__global__ void __launch_bounds__(256) k_half(const float* __restrict__ img)
{
    __shared__ float tile[32][TPX + 1];            // [c_local][px]
    const int b   = blockIdx.z;
    const int c0  = blockIdx.y * 32;
    const int hw0 = blockIdx.x * TPX;
    const int tid = threadIdx.x;

    // early, independent mark load: latency overlaps the staging loop
    const int px = tid >> 2;        // 0..63
    const int q  = tid & 3;         // octet 0..3 -> channels 8q..8q+7
    const unsigned char mk = g_mark[(size_t)b * HW + hw0 + px];

    // staging: 32 rows x 64 px, warp = 32 contiguous px of one c row
    const float* __restrict__ src = img + ((size_t)b * CC + c0) * HW + hw0;
    #pragma unroll
    for (int it = 0; it < 8; it++) {
        const int i  = it * 256 + tid;
        const int ppx = i & 63;
        const int c   = i >> 6;
        tile[c][ppx] = __ldcs(src + (size_t)c * HW + ppx);
    }
    __syncthreads();

    float v[8];
    #pragma unroll
    for (int j = 0; j < 8; j++) v[j] = tile[8 * q + j][px];

    uint4 uh, ul;
    unsigned int* ph = reinterpret_cast<unsigned int*>(&uh);
    unsigned int* pl = reinterpret_cast<unsigned int*>(&ul);
    #pragma unroll
    for (int j = 0; j < 4; j++) {
        const float2 f = make_float2(v[2 * j], v[2 * j + 1]);
        const __half2 h2 = __float22half2_rn(f);
        const float2 fb = __half22float2(h2);
        const float2 r = make_float2(f.x - fb.x, f.y - fb.y);   // exact
        const __half2 l2 = __float22half2_rn(r);
        ph[j] = *reinterpret_cast<const unsigned int*>(&h2);
        pl[j] = *reinterpret_cast<const unsigned int*>(&l2);
    }
    const size_t off = (size_t)(b * HW + hw0 + px) * CC + c0 + 8 * q;
    *reinterpret_cast<uint4*>(g_h + off) = uh;
    if (mk)
        *reinterpret_cast<uint4*>(g_l + off) = ul;
}

// ---------------------------------------------------------------------------
// k_delta: warp = point (8 points / 256-thread block, grid 2500*BB/8).
//  - 4 center taps from hi+lo (lane = 4 channels) -> fp32 feature
//  - 16 dot products with conv rows 2..17 (float4 cw loads + shfl tree)
//  - 9 locations -> tap offsets + weights written to scratch
// ---------------------------------------------------------------------------
__global__ void __launch_bounds__(256) k_delta(
    const float* __restrict__ verts,
    const float* __restrict__ cw,
    const float* __restrict__ cb)
{
    const int warp = threadIdx.x >> 5;
    const int lane = threadIdx.x & 31;
    const int p = blockIdx.x * 8 + warp;
    if (p >= BB * NN) return;
    const int b = p / NN;

    const float vx = verts[p * 2 + 0];
    const float vy = verts[p * 2 + 1];

    const float gx = clampf((vx + 1.0f) * 0.5f * (WW - 1), 0.0f, (float)(WW - 1));
    const float gy = clampf((vy + 1.0f) * 0.5f * (HH - 1), 0.0f, (float)(HH - 1));
    const int x0 = (int)floorf(gx), y0 = (int)floorf(gy);
    const int x1 = min(x0 + 1, WW - 1), y1 = min(y0 + 1, HH - 1);
    const float wx1 = gx - (float)x0, wy1 = gy - (float)y0;
    const float wx0 = 1.0f - wx1, wy0 = 1.0f - wy1;

    const size_t base = (size_t)b * HW * CC;
    const size_t lo4 = lane * 4;

    // 4 taps, batched loads
    const size_t o00 = base + (size_t)(y0 * WW + x0) * CC + lo4;
    const size_t o01 = base + (size_t)(y0 * WW + x1) * CC + lo4;
    const size_t o10 = base + (size_t)(y1 * WW + x0) * CC + lo4;
    const size_t o11 = base + (size_t)(y1 * WW + x1) * CC + lo4;
    const uint2 uh0 = *reinterpret_cast<const uint2*>(g_h + o00);
    const uint2 uh1 = *reinterpret_cast<const uint2*>(g_h + o01);
    const uint2 uh2 = *reinterpret_cast<const uint2*>(g_h + o10);
    const uint2 uh3 = *reinterpret_cast<const uint2*>(g_h + o11);
    const uint2 ul0 = *reinterpret_cast<const uint2*>(g_l + o00);
    const uint2 ul1 = *reinterpret_cast<const uint2*>(g_l + o01);
    const uint2 ul2 = *reinterpret_cast<const uint2*>(g_l + o10);
    const uint2 ul3 = *reinterpret_cast<const uint2*>(g_l + o11);

    float4 f = make_float4(0.f, 0.f, 0.f, 0.f);
    {
        const float w[4] = {wy0 * wx0, wy0 * wx1, wy1 * wx0, wy1 * wx1};
        const uint2 uhs[4] = {uh0, uh1, uh2, uh3};
        const uint2 uls[4] = {ul0, ul1, ul2, ul3};
        #pragma unroll
        for (int t = 0; t < 4; t++) {
            const float2 a0 = __half22float2(*reinterpret_cast<const __half2*>(&uhs[t].x));
            const float2 a1 = __half22float2(*reinterpret_cast<const __half2*>(&uhs[t].y));
            const float2 b0 = __half22float2(*reinterpret_cast<const __half2*>(&uls[t].x));
            const float2 b1 = __half22float2(*reinterpret_cast<const __half2*>(&uls[t].y));
            f.x = fmaf(a0.x + b0.x, w[t], f.x);
            f.y = fmaf(a0.y + b0.y, w[t], f.y);
            f.z = fmaf(a1.x + b1.x, w[t], f.z);
            f.w = fmaf(a1.y + b1.y, w[t], f.w);
        }
    }

    // 16 dot products
    __shared__ float sd_all[8][16];
    #pragma unroll
    for (int o = 0; o < 16; o++) {
        const float4 w4 = *reinterpret_cast<const float4*>(cw + (o + 2) * CC + lo4);
        float s = f.x * w4.x + f.y * w4.y + f.z * w4.z + f.w * w4.w;
        s += __shfl_down_sync(0xffffffffu, s, 16);
        s += __shfl_down_sync(0xffffffffu, s, 8);
        s += __shfl_down_sync(0xffffffffu, s, 4);
        s += __shfl_down_sync(0xffffffffu, s, 2);
        s += __shfl_down_sync(0xffffffffu, s, 1);
        if (lane == 0) sd_all[warp][o] = s + cb[o + 2];
    }
    __syncwarp();

    // 9 locations (lane 0 = center, 1..8 = learnt)
    if (lane < 9) {
        float nx = vx, ny = vy;
        if (lane > 0) {
            nx += sd_all[warp][2 * lane - 2];
            ny += sd_all[warp][2 * lane - 1];
        }
        const float ggx = clampf((nx + 1.0f) * 0.5f * (WW - 1), 0.0f, (float)(WW - 1));
        const float ggy = clampf((ny + 1.0f) * 0.5f * (HH - 1), 0.0f, (float)(HH - 1));
        const int nx0 = (int)floorf(ggx), ny0 = (int)floorf(ggy);
        const int nx1 = min(nx0 + 1, WW - 1), ny1 = min(ny0 + 1, HH - 1);
        const float nwx1 = ggx - (float)nx0, nwy1 = ggy - (float)ny0;
        const float nwx0 = 1.0f - nwx1, nwy0 = 1.0f - nwy1;
        int4 so;
        so.x = (ny0 * WW + nx0) * CC;
        so.y = (ny0 * WW + nx1) * CC;
        so.z = (ny1 * WW + nx0) * CC;
        so.w = (ny1 * WW + nx1) * CC;
        const float s = 1.0f / 9.0f;
        float4 sw;
        sw.x = nwy0 * nwx0 * s;
        sw.y = nwy0 * nwx1 * s;
        sw.z = nwy1 * nwx0 * s;
        sw.w = nwy1 * nwx1 * s;
        g_soff[p * 9 + lane] = so;
        g_swt [p * 9 + lane] = sw;
    }
}

// ---------------------------------------------------------------------------
// k_gather: one block per point (128 threads) — pure 36-tap gather (R3 form).
// grp = tap j of all 9 locations; lane = 4 channels.
// ---------------------------------------------------------------------------
__global__ void __launch_bounds__(128, 16) k_gather(float* __restrict__ out)
{
    const int p = blockIdx.x;            // 0 .. B*N-1
    const int b = p / NN;
    const int tid = threadIdx.x;
    const int lane = tid & 31, grp = tid >> 5;

    __shared__ int4   soff[9];
    __shared__ float4 swt[9];
    if (tid < 9) {
        soff[tid] = g_soff[p * 9 + tid];
        swt[tid]  = g_swt [p * 9 + tid];
    }
    __syncthreads();

    const __half* hb = g_h + (size_t)b * HW * CC + lane * 4;
    const int*   so = reinterpret_cast<const int*>(soff);
    const float* sw = reinterpret_cast<const float*>(swt);

    float ax = 0.f, ay = 0.f, az = 0.f, aw = 0.f;
    #pragma unroll
    for (int i = 0; i < 9; i++) {
        const int off = so[i * 4 + grp];
        const float w = sw[i * 4 + grp];
        const uint2 u = *reinterpret_cast<const uint2*>(hb + off);
        const float2 f0 = __half22float2(*reinterpret_cast<const __half2*>(&u.x));
        const float2 f1 = __half22float2(*reinterpret_cast<const __half2*>(&u.y));
        ax = fmaf(w, f0.x, ax); ay = fmaf(w, f0.y, ay);
        az = fmaf(w, f1.x, az); aw = fmaf(w, f1.y, aw);
    }

    __shared__ float4 red[4][32];
    red[grp][lane] = make_float4(ax, ay, az, aw);
    __syncthreads();

    if (tid < 32) {
        const float4 r0 = red[0][tid], r1 = red[1][tid];
        const float4 r2 = red[2][tid], r3 = red[3][tid];
        float4 o4;
        o4.x = r0.x + r1.x + r2.x + r3.x;
        o4.y = r0.y + r1.y + r2.y + r3.y;
        o4.z = r0.z + r1.z + r2.z + r3.z;
        o4.w = r0.w + r1.w + r2.w + r3.w;
        reinterpret_cast<float4*>(out)[(size_t)p * 32 + tid] = o4;
    }
}

extern "C" void kernel_launch(void* const* d_in, const int* in_sizes, int n_in,
                              void* d_out, int out_size)
{
    const float* img   = (const float*)d_in[0];   // (B, C, H, W)
    const float* verts = (const float*)d_in[1];   // (B, N, 2)
    const float* cw    = (const float*)d_in[2];   // (18, C)
    const float* cb    = (const float*)d_in[3];   // (18,)
    float* out = (float*)d_out;                   // (B, N, C)

    // clear mark map (capturable memset node; no allocation)
    void* mark_ptr = nullptr;
    cudaGetSymbolAddress(&mark_ptr, g_mark);
    cudaMemsetAsync(mark_ptr, 0, (size_t)BB * HW);

    k_mark<<<(BB * NN + 255) / 256, 256>>>(verts);

    dim3 tgrid(HW / TPX, CC / 32, BB);
    k_half<<<tgrid, 256>>>(img);

    k_delta<<<(BB * NN + 7) / 8, 256>>>(verts, cw, cb);
    k_gather<<<BB * NN, 128>>>(out);
}

// round 17
// speedup vs baseline: 1.2416x; 1.0848x over previous
#include <cuda_runtime.h>
#include <cuda_fp16.h>

// Problem constants (B=2, C=128, H=800, W=640, N=10000)
#define BB 2
#define CC 128
#define HH 800
#define WW 640
#define NN 10000
#define HW (HH * WW)      // 512000
#define TPX 64            // pixels per transpose tile

// Scratch
__device__ __half g_h[(size_t)BB * HW * CC];       // 262 MB  fp16 hi plane (full)
__device__ __half g_l[(size_t)BB * HW * CC];       // 262 MB  fp16 lo plane (sparse)
__device__ unsigned char g_mark[(size_t)BB * HW];  // 1 MB    pixel needs lo plane
__device__ int4   g_soff[(size_t)BB * NN * 9];     // 2.9 MB  tap offsets per location
__device__ float4 g_swt [(size_t)BB * NN * 9];     // 2.9 MB  tap weights  per location

__device__ __forceinline__ float clampf(float v, float lo, float hi) {
    return fminf(fmaxf(v, lo), hi);
}

// ---------------------------------------------------------------------------
// k_mark: thread = point; mark the 4 center-tap pixels. Idempotent stores.
// (g_mark starts all-zero: zero-initialized at load, and k_delta re-clears
//  every marked pixel each launch.)
// ---------------------------------------------------------------------------
__global__ void __launch_bounds__(256) k_mark(const float* __restrict__ verts)
{
    const int p = blockIdx.x * 256 + threadIdx.x;
    if (p >= BB * NN) return;
    const int b = p / NN;

    const float vx = verts[p * 2 + 0];
    const float vy = verts[p * 2 + 1];
    const float gx = clampf((vx + 1.0f) * 0.5f * (WW - 1), 0.0f, (float)(WW - 1));
    const float gy = clampf((vy + 1.0f) * 0.5f * (HH - 1), 0.0f, (float)(HH - 1));
    const int x0 = (int)floorf(gx), y0 = (int)floorf(gy);
    const int x1 = min(x0 + 1, WW - 1), y1 = min(y0 + 1, HH - 1);

    unsigned char* m = g_mark + (size_t)b * HW;
    m[y0 * WW + x0] = 1;
    m[y0 * WW + x1] = 1;
    m[y1 * WW + x0] = 1;
    m[y1 * WW + x1] = 1;
}

// ---------------------------------------------------------------------------
// k_half: transpose (B,C,H,W) fp32 -> (B,H,W,C) fp16 hi (always) + lo (only
// at marked pixels). grid = (HW/64, C/32, B), block = 256.
// Staging uses LDG.128 (2 float4 per thread).
// ---------------------------------------------------------------------------
__global__ void __launch_bounds__(256) k_half(const float* __restrict__ img)
{
    __shared__ float tile[32][TPX + 1];            // [c_local][px], pad 65
    const int b   = blockIdx.z;
    const int c0  = blockIdx.y * 32;
    const int hw0 = blockIdx.x * TPX;
    const int tid = threadIdx.x;

    // early, independent mark load: latency overlaps the staging loads
    const int px = tid >> 2;        // 0..63
    const int q  = tid & 3;         // octet 0..3 -> channels 8q..8q+7
    const unsigned char mk = g_mark[(size_t)b * HW + hw0 + px];

    // staging: 32 rows x 64 px as 2x float4 per thread (LDG.128, evict-first)
    const float4* __restrict__ src4 =
        reinterpret_cast<const float4*>(img + ((size_t)b * CC + c0) * HW + hw0);
    const size_t cstride = HW / 4;
    #pragma unroll
    for (int it = 0; it < 2; it++) {
        const int i = it * 256 + tid;
        const int c = i >> 4;       // 0..31
        const int f = i & 15;       // float4 index within row
        const float4 v4 = __ldcs(src4 + (size_t)c * cstride + f);
        tile[c][4 * f + 0] = v4.x;
        tile[c][4 * f + 1] = v4.y;
        tile[c][4 * f + 2] = v4.z;
        tile[c][4 * f + 3] = v4.w;
    }
    __syncthreads();

    float v[8];
    #pragma unroll
    for (int j = 0; j < 8; j++) v[j] = tile[8 * q + j][px];

    uint4 uh, ul;
    unsigned int* ph = reinterpret_cast<unsigned int*>(&uh);
    unsigned int* pl = reinterpret_cast<unsigned int*>(&ul);
    #pragma unroll
    for (int j = 0; j < 4; j++) {
        const float2 f = make_float2(v[2 * j], v[2 * j + 1]);
        const __half2 h2 = __float22half2_rn(f);
        const float2 fb = __half22float2(h2);
        const float2 r = make_float2(f.x - fb.x, f.y - fb.y);   // exact
        const __half2 l2 = __float22half2_rn(r);
        ph[j] = *reinterpret_cast<const unsigned int*>(&h2);
        pl[j] = *reinterpret_cast<const unsigned int*>(&l2);
    }
    const size_t off = (size_t)(b * HW + hw0 + px) * CC + c0 + 8 * q;
    *reinterpret_cast<uint4*>(g_h + off) = uh;
    if (mk)
        *reinterpret_cast<uint4*>(g_l + off) = ul;
}

// ---------------------------------------------------------------------------
// k_delta: warp = point (8 points / 256-thread block).
//  - 4 center taps from hi+lo (lane = 4 channels) -> fp32 feature
//  - 16 dot products with conv rows 2..17 (float4 cw loads + shfl tree)
//  - 9 locations -> tap offsets + weights written to scratch
//  - clears this point's 4 mark bytes (restores all-zero map for next launch)
// ---------------------------------------------------------------------------
__global__ void __launch_bounds__(256) k_delta(
    const float* __restrict__ verts,
    const float* __restrict__ cw,
    const float* __restrict__ cb)
{
    const int warp = threadIdx.x >> 5;
    const int lane = threadIdx.x & 31;
    const int p = blockIdx.x * 8 + warp;
    if (p >= BB * NN) return;
    const int b = p / NN;

    const float vx = verts[p * 2 + 0];
    const float vy = verts[p * 2 + 1];

    const float gx = clampf((vx + 1.0f) * 0.5f * (WW - 1), 0.0f, (float)(WW - 1));
    const float gy = clampf((vy + 1.0f) * 0.5f * (HH - 1), 0.0f, (float)(HH - 1));
    const int x0 = (int)floorf(gx), y0 = (int)floorf(gy);
    const int x1 = min(x0 + 1, WW - 1), y1 = min(y0 + 1, HH - 1);
    const float wx1 = gx - (float)x0, wy1 = gy - (float)y0;
    const float wx0 = 1.0f - wx1, wy0 = 1.0f - wy1;

    const size_t base = (size_t)b * HW * CC;
    const size_t lo4 = lane * 4;

    // 4 taps, batched loads
    const size_t o00 = base + (size_t)(y0 * WW + x0) * CC + lo4;
    const size_t o01 = base + (size_t)(y0 * WW + x1) * CC + lo4;
    const size_t o10 = base + (size_t)(y1 * WW + x0) * CC + lo4;
    const size_t o11 = base + (size_t)(y1 * WW + x1) * CC + lo4;
    const uint2 uh0 = *reinterpret_cast<const uint2*>(g_h + o00);
    const uint2 uh1 = *reinterpret_cast<const uint2*>(g_h + o01);
    const uint2 uh2 = *reinterpret_cast<const uint2*>(g_h + o10);
    const uint2 uh3 = *reinterpret_cast<const uint2*>(g_h + o11);
    const uint2 ul0 = *reinterpret_cast<const uint2*>(g_l + o00);
    const uint2 ul1 = *reinterpret_cast<const uint2*>(g_l + o01);
    const uint2 ul2 = *reinterpret_cast<const uint2*>(g_l + o10);
    const uint2 ul3 = *reinterpret_cast<const uint2*>(g_l + o11);

    // clear marks for next launch (all-zero stores; idempotent across points)
    if (lane == 0) {
        unsigned char* m = g_mark + (size_t)b * HW;
        m[y0 * WW + x0] = 0;
        m[y0 * WW + x1] = 0;
        m[y1 * WW + x0] = 0;
        m[y1 * WW + x1] = 0;
    }

    float4 f = make_float4(0.f, 0.f, 0.f, 0.f);
    {
        const float w[4] = {wy0 * wx0, wy0 * wx1, wy1 * wx0, wy1 * wx1};
        const uint2 uhs[4] = {uh0, uh1, uh2, uh3};
        const uint2 uls[4] = {ul0, ul1, ul2, ul3};
        #pragma unroll
        for (int t = 0; t < 4; t++) {
            const float2 a0 = __half22float2(*reinterpret_cast<const __half2*>(&uhs[t].x));
            const float2 a1 = __half22float2(*reinterpret_cast<const __half2*>(&uhs[t].y));
            const float2 b0 = __half22float2(*reinterpret_cast<const __half2*>(&uls[t].x));
            const float2 b1 = __half22float2(*reinterpret_cast<const __half2*>(&uls[t].y));
            f.x = fmaf(a0.x + b0.x, w[t], f.x);
            f.y = fmaf(a0.y + b0.y, w[t], f.y);
            f.z = fmaf(a1.x + b1.x, w[t], f.z);
            f.w = fmaf(a1.y + b1.y, w[t], f.w);
        }
    }

    // 16 dot products
    __shared__ float sd_all[8][16];
    #pragma unroll
    for (int o = 0; o < 16; o++) {
        const float4 w4 = *reinterpret_cast<const float4*>(cw + (o + 2) * CC + lo4);
        float s = f.x * w4.x + f.y * w4.y + f.z * w4.z + f.w * w4.w;
        s += __shfl_down_sync(0xffffffffu, s, 16);
        s += __shfl_down_sync(0xffffffffu, s, 8);
        s += __shfl_down_sync(0xffffffffu, s, 4);
        s += __shfl_down_sync(0xffffffffu, s, 2);
        s += __shfl_down_sync(0xffffffffu, s, 1);
        if (lane == 0) sd_all[warp][o] = s + cb[o + 2];
    }
    __syncwarp();

    // 9 locations (lane 0 = center, 1..8 = learnt)
    if (lane < 9) {
        float nx = vx, ny = vy;
        if (lane > 0) {
            nx += sd_all[warp][2 * lane - 2];
            ny += sd_all[warp][2 * lane - 1];
        }
        const float ggx = clampf((nx + 1.0f) * 0.5f * (WW - 1), 0.0f, (float)(WW - 1));
        const float ggy = clampf((ny + 1.0f) * 0.5f * (HH - 1), 0.0f, (float)(HH - 1));
        const int nx0 = (int)floorf(ggx), ny0 = (int)floorf(ggy);
        const int nx1 = min(nx0 + 1, WW - 1), ny1 = min(ny0 + 1, HH - 1);
        const float nwx1 = ggx - (float)nx0, nwy1 = ggy - (float)ny0;
        const float nwx0 = 1.0f - nwx1, nwy0 = 1.0f - nwy1;
        int4 so;
        so.x = (ny0 * WW + nx0) * CC;
        so.y = (ny0 * WW + nx1) * CC;
        so.z = (ny1 * WW + nx0) * CC;
        so.w = (ny1 * WW + nx1) * CC;
        const float s = 1.0f / 9.0f;
        float4 sw;
        sw.x = nwy0 * nwx0 * s;
        sw.y = nwy0 * nwx1 * s;
        sw.z = nwy1 * nwx0 * s;
        sw.w = nwy1 * nwx1 * s;
        g_soff[p * 9 + lane] = so;
        g_swt [p * 9 + lane] = sw;
    }
}

// ---------------------------------------------------------------------------
// k_gather: one block per point (128 threads) — pure 36-tap gather.
// grp = tap j of all 9 locations; lane = 4 channels.
// ---------------------------------------------------------------------------
__global__ void __launch_bounds__(128, 16) k_gather(float* __restrict__ out)
{
    const int p = blockIdx.x;            // 0 .. B*N-1
    const int b = p / NN;
    const int tid = threadIdx.x;
    const int lane = tid & 31, grp = tid >> 5;

    __shared__ int4   soff[9];
    __shared__ float4 swt[9];
    if (tid < 9) {
        soff[tid] = g_soff[p * 9 + tid];
        swt[tid]  = g_swt [p * 9 + tid];
    }
    __syncthreads();

    const __half* hb = g_h + (size_t)b * HW * CC + lane * 4;
    const int*   so = reinterpret_cast<const int*>(soff);
    const float* sw = reinterpret_cast<const float*>(swt);

    float ax = 0.f, ay = 0.f, az = 0.f, aw = 0.f;
    #pragma unroll
    for (int i = 0; i < 9; i++) {
        const int off = so[i * 4 + grp];
        const float w = sw[i * 4 + grp];
        const uint2 u = *reinterpret_cast<const uint2*>(hb + off);
        const float2 f0 = __half22float2(*reinterpret_cast<const __half2*>(&u.x));
        const float2 f1 = __half22float2(*reinterpret_cast<const __half2*>(&u.y));
        ax = fmaf(w, f0.x, ax); ay = fmaf(w, f0.y, ay);
        az = fmaf(w, f1.x, az); aw = fmaf(w, f1.y, aw);
    }

    __shared__ float4 red[4][32];
    red[grp][lane] = make_float4(ax, ay, az, aw);
    __syncthreads();

    if (tid < 32) {
        const float4 r0 = red[0][tid], r1 = red[1][tid];
        const float4 r2 = red[2][tid], r3 = red[3][tid];
        float4 o4;
        o4.x = r0.x + r1.x + r2.x + r3.x;
        o4.y = r0.y + r1.y + r2.y + r3.y;
        o4.z = r0.z + r1.z + r2.z + r3.z;
        o4.w = r0.w + r1.w + r2.w + r3.w;
        reinterpret_cast<float4*>(out)[(size_t)p * 32 + tid] = o4;
    }
}

extern "C" void kernel_launch(void* const* d_in, const int* in_sizes, int n_in,
                              void* d_out, int out_size)
{
    const float* img   = (const float*)d_in[0];   // (B, C, H, W)
    const float* verts = (const float*)d_in[1];   // (B, N, 2)
    const float* cw    = (const float*)d_in[2];   // (18, C)
    const float* cb    = (const float*)d_in[3];   // (18,)
    float* out = (float*)d_out;                   // (B, N, C)

    k_mark<<<(BB * NN + 255) / 256, 256>>>(verts);

    dim3 tgrid(HW / TPX, CC / 32, BB);
    k_half<<<tgrid, 256>>>(img);

    k_delta<<<(BB * NN + 7) / 8, 256>>>(verts, cw, cb);
    k_gather<<<BB * NN, 128>>>(out);
}